// round 1
// baseline (speedup 1.0000x reference)
#include <cuda_runtime.h>

// ---------------------------------------------------------------------------
// MinGRU block: x += minGRU(LN1(x)); x += FFN(LN2(x))
// B=4, T=8192, H=512. All fp32.
//
// minGRU scan done in LINEAR space: h_t = a_t*h_{t-1} + b_t,
//   a = 1-sigmoid(k), b = sigmoid(k)*g(hpre),  g(x)= x+0.5 (x>=0) else sigmoid(x)
// which is exactly exp() of the reference's log-space recurrence (all terms
// positive, O(1) magnitudes -> numerically safe in fp32).
// ---------------------------------------------------------------------------

#define BDIM 4
#define TDIM 8192
#define HDIM 512
#define MDIM (BDIM * TDIM)          // 32768 tokens
#define MH   (MDIM * HDIM)          // 16,777,216 elements
#define CHUNK 64
#define NCH  (TDIM / CHUNK)         // 128 chunks per batch

// scratch (device globals: allocation-free)
__device__ float g_A [MH];          // LN outputs (reused for LN1 and LN2)
__device__ float g_k [MH];          // k preact -> a ; later reused for h1
__device__ float g_hp[MH];          // h preact -> b
__device__ float g_x2[MH];          // residual after GRU branch
__device__ float g_Ac[BDIM * NCH * HDIM];
__device__ float g_Bc[BDIM * NCH * HDIM];
__device__ float g_Hc[BDIM * NCH * HDIM];

// ------------------------------- LayerNorm --------------------------------
// one block per token, 128 threads, 4 floats/thread (float4)
__global__ void ln_kernel(const float* __restrict__ x,
                          const float* __restrict__ gw,
                          const float* __restrict__ bw,
                          float* __restrict__ out) {
    int row = blockIdx.x;
    int tid = threadIdx.x;
    const float4* xr = reinterpret_cast<const float4*>(x) + row * (HDIM / 4);
    float4 v = xr[tid];
    float s  = v.x + v.y + v.z + v.w;
    float sq = v.x * v.x + v.y * v.y + v.z * v.z + v.w * v.w;
#pragma unroll
    for (int o = 16; o; o >>= 1) {
        s  += __shfl_xor_sync(0xffffffffu, s,  o);
        sq += __shfl_xor_sync(0xffffffffu, sq, o);
    }
    __shared__ float ss[4], sqq[4];
    int w = tid >> 5, l = tid & 31;
    if (l == 0) { ss[w] = s; sqq[w] = sq; }
    __syncthreads();
    s  = ss[0]  + ss[1]  + ss[2]  + ss[3];
    sq = sqq[0] + sqq[1] + sqq[2] + sqq[3];
    float mu  = s * (1.0f / HDIM);
    float var = sq * (1.0f / HDIM) - mu * mu;
    float inv = rsqrtf(var + 1e-5f);
    float4 g4 = reinterpret_cast<const float4*>(gw)[tid];
    float4 b4 = reinterpret_cast<const float4*>(bw)[tid];
    float4 o4;
    o4.x = (v.x - mu) * inv * g4.x + b4.x;
    o4.y = (v.y - mu) * inv * g4.y + b4.y;
    o4.z = (v.z - mu) * inv * g4.z + b4.z;
    o4.w = (v.w - mu) * inv * g4.w + b4.w;
    reinterpret_cast<float4*>(out)[row * (HDIM / 4) + tid] = o4;
}

// --------------------------------- SGEMM ----------------------------------
// C[M,512] = A[M,K] @ W[K,512] + bias ; EPI: 0 plain, 1 relu, 2 +residual
// 128x128 tile, BK=16, 256 threads, 8x8 per thread.
template <int EPI>
__global__ __launch_bounds__(256, 2)
void sgemm_k(const float* __restrict__ A, const float* __restrict__ W,
             const float* __restrict__ bias, const float* __restrict__ res,
             float* __restrict__ C, int K) {
    const int N = HDIM;
    __shared__ float As[16][132];   // transposed A tile (padded)
    __shared__ float Bs[16][128];
    int bx = blockIdx.x, by = blockIdx.y;
    int tid = threadIdx.x;
    int aRow = tid >> 2;            // 0..63 (covers +64 too)
    int aCol = (tid & 3) << 2;      // 0,4,8,12
    int bRow = tid >> 5;            // 0..7 (covers +8 too)
    int bCol = (tid & 31) << 2;
    int ty = tid >> 4, tx = tid & 15;
    const float* Ap = A + (by * 128) * K;
    const float* Wp = W + bx * 128;
    float acc[8][8];
#pragma unroll
    for (int i = 0; i < 8; i++)
#pragma unroll
        for (int j = 0; j < 8; j++) acc[i][j] = 0.0f;

    for (int k0 = 0; k0 < K; k0 += 16) {
        float4 a0 = *reinterpret_cast<const float4*>(Ap + aRow * K + k0 + aCol);
        float4 a1 = *reinterpret_cast<const float4*>(Ap + (aRow + 64) * K + k0 + aCol);
        float4 w0 = *reinterpret_cast<const float4*>(Wp + (k0 + bRow) * N + bCol);
        float4 w1 = *reinterpret_cast<const float4*>(Wp + (k0 + bRow + 8) * N + bCol);
        As[aCol + 0][aRow] = a0.x; As[aCol + 1][aRow] = a0.y;
        As[aCol + 2][aRow] = a0.z; As[aCol + 3][aRow] = a0.w;
        As[aCol + 0][aRow + 64] = a1.x; As[aCol + 1][aRow + 64] = a1.y;
        As[aCol + 2][aRow + 64] = a1.z; As[aCol + 3][aRow + 64] = a1.w;
        *reinterpret_cast<float4*>(&Bs[bRow][bCol])     = w0;
        *reinterpret_cast<float4*>(&Bs[bRow + 8][bCol]) = w1;
        __syncthreads();
#pragma unroll
        for (int kk = 0; kk < 16; kk++) {
            float4 af0 = *reinterpret_cast<const float4*>(&As[kk][ty * 8]);
            float4 af1 = *reinterpret_cast<const float4*>(&As[kk][ty * 8 + 4]);
            float4 bf0 = *reinterpret_cast<const float4*>(&Bs[kk][tx * 8]);
            float4 bf1 = *reinterpret_cast<const float4*>(&Bs[kk][tx * 8 + 4]);
            float ar[8] = {af0.x, af0.y, af0.z, af0.w, af1.x, af1.y, af1.z, af1.w};
            float br[8] = {bf0.x, bf0.y, bf0.z, bf0.w, bf1.x, bf1.y, bf1.z, bf1.w};
#pragma unroll
            for (int i = 0; i < 8; i++)
#pragma unroll
                for (int j = 0; j < 8; j++)
                    acc[i][j] = fmaf(ar[i], br[j], acc[i][j]);
        }
        __syncthreads();
    }
    int col0 = bx * 128 + tx * 8;
    float bia[8];
#pragma unroll
    for (int j = 0; j < 8; j++) bia[j] = bias[col0 + j];
#pragma unroll
    for (int i = 0; i < 8; i++) {
        int r = by * 128 + ty * 8 + i;
        float out[8];
#pragma unroll
        for (int j = 0; j < 8; j++) {
            float v = acc[i][j] + bia[j];
            if (EPI == 1) v = fmaxf(v, 0.0f);
            if (EPI == 2) v += res[r * N + col0 + j];
            out[j] = v;
        }
        float4* Crow = reinterpret_cast<float4*>(C + r * N + col0);
        Crow[0] = make_float4(out[0], out[1], out[2], out[3]);
        Crow[1] = make_float4(out[4], out[5], out[6], out[7]);
    }
}

// ------------------------------ gate epilogue ------------------------------
// in-place: k -> a = 1-sigmoid(k) ; hp -> b = sigmoid(k)*g(hp)
__device__ __forceinline__ void gate1(float kx, float hx, float& a, float& b) {
    float av = 1.0f / (1.0f + expf(kx));    // sigmoid(-k), saturates safely
    float zv = 1.0f / (1.0f + expf(-kx));   // sigmoid(k)
    float gv = (hx >= 0.0f) ? (hx + 0.5f) : 1.0f / (1.0f + expf(-hx));
    a = av; b = zv * gv;
}

__global__ void gate_kernel(float* __restrict__ k, float* __restrict__ hp) {
    int i = blockIdx.x * blockDim.x + threadIdx.x;
    float4 kv = reinterpret_cast<const float4*>(k)[i];
    float4 hv = reinterpret_cast<const float4*>(hp)[i];
    float4 av, bv;
    gate1(kv.x, hv.x, av.x, bv.x);
    gate1(kv.y, hv.y, av.y, bv.y);
    gate1(kv.z, hv.z, av.z, bv.z);
    gate1(kv.w, hv.w, av.w, bv.w);
    reinterpret_cast<float4*>(k)[i]  = av;
    reinterpret_cast<float4*>(hp)[i] = bv;
}

// ------------------------------- chunked scan ------------------------------
// pass 1: per (batch, chunk, h) compute chunk composition (Aprod, Bacc)
__global__ void scan_p1(const float* __restrict__ a, const float* __restrict__ b,
                        float* __restrict__ Ac, float* __restrict__ Bc) {
    int h = threadIdx.x;            // 512
    int c = blockIdx.x;             // NCH
    int bb = blockIdx.y;            // BDIM
    int base = ((bb * TDIM + c * CHUNK) * HDIM) + h;
    float Ap = 1.0f, Bv = 0.0f;
#pragma unroll 4
    for (int t = 0; t < CHUNK; t++) {
        float at = a[base + t * HDIM];
        float bt = b[base + t * HDIM];
        Bv = fmaf(at, Bv, bt);
        Ap *= at;
    }
    int o = (bb * NCH + c) * HDIM + h;
    Ac[o] = Ap;
    Bc[o] = Bv;
}

// pass 2: sequential scan over chunks -> initial h per chunk
__global__ void scan_p2(const float* __restrict__ Ac, const float* __restrict__ Bc,
                        float* __restrict__ Hc) {
    int h = threadIdx.x;
    int bb = blockIdx.x;
    float hcur = 0.5f;              // h_0 = g(0) = 0.5
    for (int c = 0; c < NCH; c++) {
        int o = (bb * NCH + c) * HDIM + h;
        Hc[o] = hcur;
        hcur = fmaf(Ac[o], hcur, Bc[o]);
    }
}

// pass 3: replay within chunk with correct init; x2 = x + h
__global__ void scan_p3(const float* __restrict__ a, const float* __restrict__ b,
                        const float* __restrict__ Hc, const float* __restrict__ x,
                        float* __restrict__ x2) {
    int h = threadIdx.x;
    int c = blockIdx.x;
    int bb = blockIdx.y;
    int base = ((bb * TDIM + c * CHUNK) * HDIM) + h;
    float hcur = Hc[(bb * NCH + c) * HDIM + h];
#pragma unroll 4
    for (int t = 0; t < CHUNK; t++) {
        int idx = base + t * HDIM;
        hcur = fmaf(a[idx], hcur, b[idx]);
        x2[idx] = x[idx] + hcur;
    }
}

// --------------------------------- launch ----------------------------------
extern "C" void kernel_launch(void* const* d_in, const int* in_sizes, int n_in,
                              void* d_out, int out_size) {
    const float* x     = (const float*)d_in[0];
    const float* ln1_g = (const float*)d_in[1];
    const float* ln1_b = (const float*)d_in[2];
    const float* Wz    = (const float*)d_in[3];
    const float* bz    = (const float*)d_in[4];
    const float* Wh    = (const float*)d_in[5];
    const float* bh    = (const float*)d_in[6];
    const float* ln2_g = (const float*)d_in[7];
    const float* ln2_b = (const float*)d_in[8];
    const float* W1    = (const float*)d_in[9];
    const float* b1    = (const float*)d_in[10];
    const float* W2    = (const float*)d_in[11];
    const float* b2    = (const float*)d_in[12];
    float* out = (float*)d_out;

    float *pA, *pK, *pHp, *pX2, *pAc, *pBc, *pHc;
    cudaGetSymbolAddress((void**)&pA,  g_A);
    cudaGetSymbolAddress((void**)&pK,  g_k);
    cudaGetSymbolAddress((void**)&pHp, g_hp);
    cudaGetSymbolAddress((void**)&pX2, g_x2);
    cudaGetSymbolAddress((void**)&pAc, g_Ac);
    cudaGetSymbolAddress((void**)&pBc, g_Bc);
    cudaGetSymbolAddress((void**)&pHc, g_Hc);

    dim3 ggrid(HDIM / 128, MDIM / 128);

    // LN1
    ln_kernel<<<MDIM, 128>>>(x, ln1_g, ln1_b, pA);
    // k = A@Wz+bz ; hpre = A@Wh+bh
    sgemm_k<0><<<ggrid, 256>>>(pA, Wz, bz, nullptr, pK,  HDIM);
    sgemm_k<0><<<ggrid, 256>>>(pA, Wh, bh, nullptr, pHp, HDIM);
    // gates -> (a, b)
    gate_kernel<<<MH / 4 / 256, 256>>>(pK, pHp);
    // chunked linear scan
    scan_p1<<<dim3(NCH, BDIM), HDIM>>>(pK, pHp, pAc, pBc);
    scan_p2<<<BDIM, HDIM>>>(pAc, pBc, pHc);
    scan_p3<<<dim3(NCH, BDIM), HDIM>>>(pK, pHp, pHc, x, pX2);
    // LN2
    ln_kernel<<<MDIM, 128>>>(pX2, ln2_g, ln2_b, pA);
    // h1 = relu(A@W1+b1)
    sgemm_k<1><<<ggrid, 256>>>(pA, W1, b1, nullptr, pK, HDIM);
    // out = x2 + h1@W2 + b2
    sgemm_k<2><<<ggrid, 256>>>(pK, W2, b2, pX2, out, HDIM);
}

// round 3
// speedup vs baseline: 1.3037x; 1.3037x over previous
#include <cuda_runtime.h>
#include <cuda_bf16.h>
#include <cstdint>

// ---------------------------------------------------------------------------
// MinGRU block on GB300 (sm_103a, compiled via compute_103 => legacy mma.sync).
//   x += minGRU(LN1(x));  x += FFN(LN2(x))
// B=4, T=8192, H=512, fp32 I/O.
//
// GEMMs: fp32 operands split to bf16 hi+lo in registers while staging to
// SMEM; 3 HMMA products (ah*bh + ah*bl + al*bh) accumulate in fp32 frags.
// minGRU scan in linear space (exact exp of reference's log-space scan).
// ---------------------------------------------------------------------------

#define BDIM 4
#define TDIM 8192
#define HDIM 512
#define MDIM (BDIM * TDIM)
#define MH   (MDIM * HDIM)
#define CHUNK 64
#define NCH  (TDIM / CHUNK)

// scratch (device globals: allocation-free)
__device__ float g_A  [MH];                  // LN output (GEMM input)
__device__ float g_kh [MDIM * 1024];         // fused [k | hpre] preacts
__device__ float g_x2 [MH];                  // residual after GRU branch
__device__ float g_h1 [MH];                  // FFN hidden
__device__ float g_Wzh[1024 * 512];          // [Wz^T ; Wh^T] (N-major, K contig)
__device__ float g_W1t[512 * 512];
__device__ float g_W2t[512 * 512];
__device__ float g_bzh[1024];
__device__ float g_Ac [BDIM * NCH * HDIM];
__device__ float g_Bc [BDIM * NCH * HDIM];
__device__ float g_Hc [BDIM * NCH * HDIM];

// ============================ PTX helpers ==================================
__device__ __forceinline__ uint32_t smem_u32(const void* p) {
    uint32_t a;
    asm("{ .reg .u64 t; cvta.to.shared.u64 t, %1; cvt.u32.u64 %0, t; }"
        : "=r"(a) : "l"(p));
    return a;
}

__device__ __forceinline__ void ldsm4(uint32_t& r0, uint32_t& r1,
                                      uint32_t& r2, uint32_t& r3, uint32_t addr) {
    asm volatile("ldmatrix.sync.aligned.m8n8.x4.shared.b16 {%0,%1,%2,%3}, [%4];"
                 : "=r"(r0), "=r"(r1), "=r"(r2), "=r"(r3) : "r"(addr));
}

__device__ __forceinline__ void mma16816(float* d, const uint32_t* a,
                                         uint32_t b0, uint32_t b1) {
    asm volatile(
        "mma.sync.aligned.m16n8k16.row.col.f32.bf16.bf16.f32 "
        "{%0,%1,%2,%3}, {%4,%5,%6,%7}, {%8,%9}, {%0,%1,%2,%3};"
        : "+f"(d[0]), "+f"(d[1]), "+f"(d[2]), "+f"(d[3])
        : "r"(a[0]), "r"(a[1]), "r"(a[2]), "r"(a[3]), "r"(b0), "r"(b1));
}

__device__ __forceinline__ uint32_t pack_bf(float a, float b) {
    __nv_bfloat162 t = __floats2bfloat162_rn(a, b);
    return *reinterpret_cast<uint32_t*>(&t);
}

// smem tile: 128 rows x 64 bf16 (128B rows), XOR swizzle on 16B units
__device__ __forceinline__ uint32_t sw_off(int row, int unit) {
    return (uint32_t)row * 128u + (uint32_t)((unit ^ (row & 7)) << 4);
}

// ============================ GEMM kernel ==================================
// C[M, Ntot] = A[M,512] @ Bt^T + bias, Bt is [Ntot,512] K-contiguous.
// EPI: 0 plain, 1 relu, 2 +res.
static constexpr int TILE_B   = 128 * 128;     // bytes per bf16 tile
static constexpr int STAGE_B  = 4 * TILE_B;    // Ahi|Alo|Bhi|Blo = 64KB
static constexpr int SMEM_TOT = 2 * STAGE_B;   // 128KB

template <int EPI>
__global__ __launch_bounds__(256, 1)
void mma_gemm(const float* __restrict__ A, const float* __restrict__ Bt,
              const float* __restrict__ bias, const float* __restrict__ res,
              float* __restrict__ C, int Ntot) {
    extern __shared__ char smem[];
    const int tid = threadIdx.x, wid = tid >> 5, lane = tid & 31;
    const int m0 = blockIdx.y * 128, n0 = blockIdx.x * 128;
    const int wm = (wid >> 1) * 32;      // 4 warps down M
    const int wn = (wid & 1) * 64;       // 2 warps across N
    const uint32_t sbase = smem_u32(smem);

    const float* Ag = A  + (size_t)m0 * 512;
    const float* Bg = Bt + (size_t)n0 * 512;

    float acc[2][8][4];
#pragma unroll
    for (int i = 0; i < 2; i++)
#pragma unroll
        for (int j = 0; j < 8; j++)
#pragma unroll
            for (int l = 0; l < 4; l++) acc[i][j][l] = 0.0f;

    float4 pa[8], pb[8];   // prefetch regs: 4 units x (2 float4) each

#define LDG_TILE(G, P, c)                                                     \
    {                                                                         \
        _Pragma("unroll")                                                     \
        for (int s = 0; s < 4; s++) {                                         \
            int idx = tid + s * 256;                                          \
            int row = idx >> 3, uu = idx & 7;                                 \
            const float4* src = reinterpret_cast<const float4*>(              \
                (G) + (size_t)row * 512 + (c) * 64 + uu * 8);                 \
            (P)[2 * s] = src[0]; (P)[2 * s + 1] = src[1];                     \
        }                                                                     \
    }

#define STS_TILE(HI, LO, P)                                                   \
    {                                                                         \
        _Pragma("unroll")                                                     \
        for (int s = 0; s < 4; s++) {                                         \
            int idx = tid + s * 256;                                          \
            int row = idx >> 3, uu = idx & 7;                                 \
            float f[8] = {(P)[2*s].x, (P)[2*s].y, (P)[2*s].z, (P)[2*s].w,     \
                          (P)[2*s+1].x, (P)[2*s+1].y, (P)[2*s+1].z,           \
                          (P)[2*s+1].w};                                      \
            float h[8];                                                       \
            uint4 vh, vl;                                                     \
            _Pragma("unroll")                                                 \
            for (int j = 0; j < 8; j++)                                       \
                h[j] = __bfloat162float(__float2bfloat16(f[j]));              \
            vh.x = pack_bf(f[0], f[1]); vh.y = pack_bf(f[2], f[3]);           \
            vh.z = pack_bf(f[4], f[5]); vh.w = pack_bf(f[6], f[7]);           \
            vl.x = pack_bf(f[0]-h[0], f[1]-h[1]);                             \
            vl.y = pack_bf(f[2]-h[2], f[3]-h[3]);                             \
            vl.z = pack_bf(f[4]-h[4], f[5]-h[5]);                             \
            vl.w = pack_bf(f[6]-h[6], f[7]-h[7]);                             \
            uint32_t off = sw_off(row, uu);                                   \
            *reinterpret_cast<uint4*>(smem + (HI) + off) = vh;                \
            *reinterpret_cast<uint4*>(smem + (LO) + off) = vl;                \
        }                                                                     \
    }

    LDG_TILE(Ag, pa, 0);
    LDG_TILE(Bg, pb, 0);

    for (int c = 0; c < 8; c++) {
        const uint32_t stB = (uint32_t)(c & 1) * STAGE_B;
        STS_TILE(stB, stB + TILE_B, pa);
        STS_TILE(stB + 2 * TILE_B, stB + 3 * TILE_B, pb);
        __syncthreads();
        if (c < 7) {
            LDG_TILE(Ag, pa, c + 1);
            LDG_TILE(Bg, pb, c + 1);
        }
        const uint32_t sAh = sbase + stB;
        const uint32_t sAl = sAh + TILE_B;
        const uint32_t sBh = sAh + 2 * TILE_B;
        const uint32_t sBl = sAh + 3 * TILE_B;
#pragma unroll
        for (int k16 = 0; k16 < 4; k16++) {
            const int lrow = lane & 15;
            const int unit = k16 * 2 + (lane >> 4);
            uint32_t ah[2][4], al[2][4], bf[8][2];
            // A hi/lo fragments (two m16 tiles)
#pragma unroll
            for (int mf = 0; mf < 2; mf++) {
                uint32_t off = sw_off(wm + mf * 16 + lrow, unit);
                ldsm4(ah[mf][0], ah[mf][1], ah[mf][2], ah[mf][3], sAh + off);
                ldsm4(al[mf][0], al[mf][1], al[mf][2], al[mf][3], sAl + off);
            }
            // B hi fragments (four n16 groups -> eight n8 frags)
#pragma unroll
            for (int g = 0; g < 4; g++) {
                uint32_t r0, r1, r2, r3;
                ldsm4(r0, r1, r2, r3, sBh + sw_off(wn + g * 16 + lrow, unit));
                bf[2 * g][0] = r0; bf[2 * g][1] = r2;
                bf[2 * g + 1][0] = r1; bf[2 * g + 1][1] = r3;
            }
#pragma unroll
            for (int mf = 0; mf < 2; mf++)
#pragma unroll
                for (int nf = 0; nf < 8; nf++) {
                    mma16816(acc[mf][nf], ah[mf], bf[nf][0], bf[nf][1]); // ah*bh
                    mma16816(acc[mf][nf], al[mf], bf[nf][0], bf[nf][1]); // al*bh
                }
            // B lo fragments (reuse bf regs)
#pragma unroll
            for (int g = 0; g < 4; g++) {
                uint32_t r0, r1, r2, r3;
                ldsm4(r0, r1, r2, r3, sBl + sw_off(wn + g * 16 + lrow, unit));
                bf[2 * g][0] = r0; bf[2 * g][1] = r2;
                bf[2 * g + 1][0] = r1; bf[2 * g + 1][1] = r3;
            }
#pragma unroll
            for (int mf = 0; mf < 2; mf++)
#pragma unroll
                for (int nf = 0; nf < 8; nf++)
                    mma16816(acc[mf][nf], ah[mf], bf[nf][0], bf[nf][1]); // ah*bl
        }
    }

    // ---------------- epilogue: bias (+relu / +residual), fp32 stores ------
    const int row0 = m0 + wm + (lane >> 2);
    const int col0 = n0 + wn + (lane & 3) * 2;
#pragma unroll
    for (int mf = 0; mf < 2; mf++) {
#pragma unroll
        for (int nf = 0; nf < 8; nf++) {
            const int col = col0 + nf * 8;
            const float b0 = bias[col], b1 = bias[col + 1];
            const int rA = row0 + mf * 16;
            const int rB = rA + 8;
            float2 vA = make_float2(acc[mf][nf][0] + b0, acc[mf][nf][1] + b1);
            float2 vB = make_float2(acc[mf][nf][2] + b0, acc[mf][nf][3] + b1);
            if (EPI == 1) {
                vA.x = fmaxf(vA.x, 0.f); vA.y = fmaxf(vA.y, 0.f);
                vB.x = fmaxf(vB.x, 0.f); vB.y = fmaxf(vB.y, 0.f);
            }
            if (EPI == 2) {
                const float2 rA2 = *reinterpret_cast<const float2*>(
                    res + (size_t)rA * Ntot + col);
                const float2 rB2 = *reinterpret_cast<const float2*>(
                    res + (size_t)rB * Ntot + col);
                vA.x += rA2.x; vA.y += rA2.y;
                vB.x += rB2.x; vB.y += rB2.y;
            }
            *reinterpret_cast<float2*>(C + (size_t)rA * Ntot + col) = vA;
            *reinterpret_cast<float2*>(C + (size_t)rB * Ntot + col) = vB;
        }
    }
#undef LDG_TILE
#undef STS_TILE
}

// ============================ LayerNorm ====================================
__global__ void ln_kernel(const float* __restrict__ x,
                          const float* __restrict__ gw,
                          const float* __restrict__ bw,
                          float* __restrict__ out) {
    int row = blockIdx.x;
    int tid = threadIdx.x;
    const float4* xr = reinterpret_cast<const float4*>(x) + (size_t)row * (HDIM / 4);
    float4 v = xr[tid];
    float s  = v.x + v.y + v.z + v.w;
    float sq = v.x * v.x + v.y * v.y + v.z * v.z + v.w * v.w;
#pragma unroll
    for (int o = 16; o; o >>= 1) {
        s  += __shfl_xor_sync(0xffffffffu, s,  o);
        sq += __shfl_xor_sync(0xffffffffu, sq, o);
    }
    __shared__ float ss[4], sqq[4];
    int w = tid >> 5, l = tid & 31;
    if (l == 0) { ss[w] = s; sqq[w] = sq; }
    __syncthreads();
    s  = ss[0]  + ss[1]  + ss[2]  + ss[3];
    sq = sqq[0] + sqq[1] + sqq[2] + sqq[3];
    float mu  = s * (1.0f / HDIM);
    float var = sq * (1.0f / HDIM) - mu * mu;
    float inv = rsqrtf(var + 1e-5f);
    float4 g4 = reinterpret_cast<const float4*>(gw)[tid];
    float4 b4 = reinterpret_cast<const float4*>(bw)[tid];
    float4 o4;
    o4.x = (v.x - mu) * inv * g4.x + b4.x;
    o4.y = (v.y - mu) * inv * g4.y + b4.y;
    o4.z = (v.z - mu) * inv * g4.z + b4.z;
    o4.w = (v.w - mu) * inv * g4.w + b4.w;
    reinterpret_cast<float4*>(out)[(size_t)row * (HDIM / 4) + tid] = o4;
}

// ====================== weight transpose + bias prep =======================
__global__ void transpose_k(const float* __restrict__ W, float* __restrict__ Wt) {
    __shared__ float tile[32][33];
    int n0 = blockIdx.x * 32, k0 = blockIdx.y * 32;
    tile[threadIdx.y][threadIdx.x] = W[(size_t)(k0 + threadIdx.y) * 512 + n0 + threadIdx.x];
    __syncthreads();
    Wt[(size_t)(n0 + threadIdx.y) * 512 + k0 + threadIdx.x] = tile[threadIdx.x][threadIdx.y];
}

__global__ void bias_cat(const float* __restrict__ bz, const float* __restrict__ bh,
                         float* __restrict__ o) {
    int i = threadIdx.x + blockIdx.x * blockDim.x;
    o[i] = (i < 512) ? bz[i] : bh[i - 512];
}

// ============================ gate + scan ==================================
__device__ __forceinline__ void gate_ab(float k, float hp, float& a, float& b) {
    float av = 1.0f / (1.0f + expf(k));     // 1 - sigmoid(k)
    float zv = 1.0f / (1.0f + expf(-k));    // sigmoid(k)
    float gv = (hp >= 0.0f) ? (hp + 0.5f) : 1.0f / (1.0f + expf(-hp));
    a = av; b = zv * gv;
}

__global__ void scan_p1(const float* __restrict__ kh,
                        float* __restrict__ Ac, float* __restrict__ Bc) {
    int h = threadIdx.x, c = blockIdx.x, bb = blockIdx.y;
    size_t base = ((size_t)(bb * TDIM + c * CHUNK)) * 1024 + h;
    float Ap = 1.0f, Bv = 0.0f;
#pragma unroll 4
    for (int t = 0; t < CHUNK; t++) {
        float k  = kh[base + (size_t)t * 1024];
        float hp = kh[base + (size_t)t * 1024 + 512];
        float a, b; gate_ab(k, hp, a, b);
        Bv = fmaf(a, Bv, b);
        Ap *= a;
    }
    int o = (bb * NCH + c) * HDIM + h;
    Ac[o] = Ap; Bc[o] = Bv;
}

__global__ void scan_p2(const float* __restrict__ Ac, const float* __restrict__ Bc,
                        float* __restrict__ Hc) {
    int h = threadIdx.x, bb = blockIdx.x;
    float hcur = 0.5f;              // h_0 = g(0)
    for (int c = 0; c < NCH; c++) {
        int o = (bb * NCH + c) * HDIM + h;
        Hc[o] = hcur;
        hcur = fmaf(Ac[o], hcur, Bc[o]);
    }
}

__global__ void scan_p3(const float* __restrict__ kh, const float* __restrict__ Hc,
                        const float* __restrict__ x, float* __restrict__ x2) {
    int h = threadIdx.x, c = blockIdx.x, bb = blockIdx.y;
    size_t base = ((size_t)(bb * TDIM + c * CHUNK)) * 1024 + h;
    size_t xb   = ((size_t)(bb * TDIM + c * CHUNK)) * 512 + h;
    float hcur = Hc[(bb * NCH + c) * HDIM + h];
#pragma unroll 4
    for (int t = 0; t < CHUNK; t++) {
        float k  = kh[base + (size_t)t * 1024];
        float hp = kh[base + (size_t)t * 1024 + 512];
        float a, b; gate_ab(k, hp, a, b);
        hcur = fmaf(a, hcur, b);
        x2[xb + (size_t)t * 512] = x[xb + (size_t)t * 512] + hcur;
    }
}

// ============================== launch =====================================
extern "C" void kernel_launch(void* const* d_in, const int* in_sizes, int n_in,
                              void* d_out, int out_size) {
    const float* x     = (const float*)d_in[0];
    const float* ln1_g = (const float*)d_in[1];
    const float* ln1_b = (const float*)d_in[2];
    const float* Wz    = (const float*)d_in[3];
    const float* bz    = (const float*)d_in[4];
    const float* Wh    = (const float*)d_in[5];
    const float* bh    = (const float*)d_in[6];
    const float* ln2_g = (const float*)d_in[7];
    const float* ln2_b = (const float*)d_in[8];
    const float* W1    = (const float*)d_in[9];
    const float* b1    = (const float*)d_in[10];
    const float* W2    = (const float*)d_in[11];
    const float* b2    = (const float*)d_in[12];
    float* out = (float*)d_out;

    float *pA, *pKH, *pX2, *pH1, *pWzh, *pW1t, *pW2t, *pBzh, *pAc, *pBc, *pHc;
    cudaGetSymbolAddress((void**)&pA,   g_A);
    cudaGetSymbolAddress((void**)&pKH,  g_kh);
    cudaGetSymbolAddress((void**)&pX2,  g_x2);
    cudaGetSymbolAddress((void**)&pH1,  g_h1);
    cudaGetSymbolAddress((void**)&pWzh, g_Wzh);
    cudaGetSymbolAddress((void**)&pW1t, g_W1t);
    cudaGetSymbolAddress((void**)&pW2t, g_W2t);
    cudaGetSymbolAddress((void**)&pBzh, g_bzh);
    cudaGetSymbolAddress((void**)&pAc,  g_Ac);
    cudaGetSymbolAddress((void**)&pBc,  g_Bc);
    cudaGetSymbolAddress((void**)&pHc,  g_Hc);

    cudaFuncSetAttribute(mma_gemm<0>, cudaFuncAttributeMaxDynamicSharedMemorySize, SMEM_TOT);
    cudaFuncSetAttribute(mma_gemm<1>, cudaFuncAttributeMaxDynamicSharedMemorySize, SMEM_TOT);
    cudaFuncSetAttribute(mma_gemm<2>, cudaFuncAttributeMaxDynamicSharedMemorySize, SMEM_TOT);

    dim3 tb(32, 32);
    dim3 tg(16, 16);
    // weight prep: Bt tiles (N-major, K contiguous) + fused bias
    transpose_k<<<tg, tb>>>(Wz, pWzh);
    transpose_k<<<tg, tb>>>(Wh, pWzh + 512 * 512);
    transpose_k<<<tg, tb>>>(W1, pW1t);
    transpose_k<<<tg, tb>>>(W2, pW2t);
    bias_cat<<<4, 256>>>(bz, bh, pBzh);

    // LN1
    ln_kernel<<<MDIM, 128>>>(x, ln1_g, ln1_b, pA);
    // [k | hpre] = LN1(x) @ [Wz | Wh] + [bz | bh]
    mma_gemm<0><<<dim3(8, MDIM / 128), 256, SMEM_TOT>>>(pA, pWzh, pBzh, pA, pKH, 1024);
    // chunked linear scan (gates computed inline)
    scan_p1<<<dim3(NCH, BDIM), HDIM>>>(pKH, pAc, pBc);
    scan_p2<<<BDIM, HDIM>>>(pAc, pBc, pHc);
    scan_p3<<<dim3(NCH, BDIM), HDIM>>>(pKH, pHc, x, pX2);
    // LN2
    ln_kernel<<<MDIM, 128>>>(pX2, ln2_g, ln2_b, pA);
    // h1 = relu(LN2 @ W1 + b1)
    mma_gemm<1><<<dim3(4, MDIM / 128), 256, SMEM_TOT>>>(pA, pW1t, b1, pA, pH1, 512);
    // out = x2 + h1 @ W2 + b2
    mma_gemm<2><<<dim3(4, MDIM / 128), 256, SMEM_TOT>>>(pH1, pW2t, b2, pX2, out, 512);
}

// round 4
// speedup vs baseline: 2.2618x; 1.7349x over previous
#include <cuda_runtime.h>
#include <cuda_bf16.h>
#include <cstdint>

// ---------------------------------------------------------------------------
// MinGRU block on GB300 (sm_103a via compute_103 => legacy mma.sync path).
//   x += minGRU(LN1(x));  x += FFN(LN2(x))
// B=4, T=8192, H=512, fp32 I/O.
//
// GEMM operands pre-split to bf16 hi+lo (outside the GEMM). Mainloop is pure
// cp.async + ldmatrix + 3x mma.sync (ah*bh + al*bh + ah*bl), fp32 accum.
// minGRU scan in linear space (exact exp of reference's log-space scan).
// ---------------------------------------------------------------------------

#define BDIM 4
#define TDIM 8192
#define HDIM 512
#define MDIM (BDIM * TDIM)
#define MH   (MDIM * HDIM)
#define CHUNK 64
#define NCH  (TDIM / CHUNK)

// scratch (device globals: allocation-free)
__device__ __nv_bfloat16 g_Ahi[MH], g_Alo[MH];     // LN output split
__device__ __nv_bfloat16 g_H1hi[MH], g_H1lo[MH];   // FFN hidden split
__device__ __nv_bfloat16 g_Wzhh[1024 * 512], g_Wzhl[1024 * 512];
__device__ __nv_bfloat16 g_W1h[512 * 512],  g_W1l[512 * 512];
__device__ __nv_bfloat16 g_W2h[512 * 512],  g_W2l[512 * 512];
__device__ float g_kh [MDIM * 1024];               // [k | hpre] preacts
__device__ float g_x2 [MH];                        // residual after GRU
__device__ float g_bzh[1024];
__device__ float g_Ac [BDIM * NCH * HDIM];
__device__ float g_Bc [BDIM * NCH * HDIM];
__device__ float g_Hc [BDIM * NCH * HDIM];

// ============================ PTX helpers ==================================
__device__ __forceinline__ uint32_t smem_u32(const void* p) {
    uint32_t a;
    asm("{ .reg .u64 t; cvta.to.shared.u64 t, %1; cvt.u32.u64 %0, t; }"
        : "=r"(a) : "l"(p));
    return a;
}
__device__ __forceinline__ void ldsm4(uint32_t& r0, uint32_t& r1,
                                      uint32_t& r2, uint32_t& r3, uint32_t addr) {
    asm volatile("ldmatrix.sync.aligned.m8n8.x4.shared.b16 {%0,%1,%2,%3}, [%4];"
                 : "=r"(r0), "=r"(r1), "=r"(r2), "=r"(r3) : "r"(addr));
}
__device__ __forceinline__ void mma16816(float* d, const uint32_t* a,
                                         uint32_t b0, uint32_t b1) {
    asm volatile(
        "mma.sync.aligned.m16n8k16.row.col.f32.bf16.bf16.f32 "
        "{%0,%1,%2,%3}, {%4,%5,%6,%7}, {%8,%9}, {%0,%1,%2,%3};"
        : "+f"(d[0]), "+f"(d[1]), "+f"(d[2]), "+f"(d[3])
        : "r"(a[0]), "r"(a[1]), "r"(a[2]), "r"(a[3]), "r"(b0), "r"(b1));
}
#define CP16(dst, src) \
    asm volatile("cp.async.cg.shared.global [%0], [%1], 16;" \
                 :: "r"(dst), "l"(src) : "memory")
#define CP_COMMIT() asm volatile("cp.async.commit_group;" ::: "memory")
#define CP_WAIT2()  asm volatile("cp.async.wait_group 2;"  ::: "memory")

// smem tile: 128 rows x 64 bf16 (128B rows), XOR swizzle on 16B units
__device__ __forceinline__ uint32_t sw_off(int row, int unit) {
    return (uint32_t)row * 128u + (uint32_t)((unit ^ (row & 7)) << 4);
}

// ============================ GEMM kernel ==================================
// C[M,Ntot] = A[M,512] @ Bt^T + bias ; A,Bt given as bf16 hi/lo pairs,
// Bt is [Ntot,512] K-contiguous. EPI: 0 fp32 out, 1 relu->bf16 hi/lo out,
// 2 +residual fp32 out.
static constexpr int TILE_B  = 128 * 128;     // 16KB per bf16 tile
static constexpr int STAGE_B = 4 * TILE_B;    // Ahi|Alo|Bhi|Blo = 64KB
static constexpr int NSTAGE  = 3;
static constexpr int SMEM_TOT = NSTAGE * STAGE_B;  // 192KB

template <int EPI>
__global__ __launch_bounds__(256, 1)
void mma_gemm(const __nv_bfloat16* __restrict__ Ahi,
              const __nv_bfloat16* __restrict__ Alo,
              const __nv_bfloat16* __restrict__ Bhi,
              const __nv_bfloat16* __restrict__ Blo,
              const float* __restrict__ bias, const float* __restrict__ res,
              float* __restrict__ Cf,
              __nv_bfloat16* __restrict__ Chi, __nv_bfloat16* __restrict__ Clo,
              int Ntot) {
    extern __shared__ char smem[];
    const int tid = threadIdx.x, wid = tid >> 5, lane = tid & 31;
    const int m0 = blockIdx.y * 128, n0 = blockIdx.x * 128;
    const int wm = (wid >> 1) * 32;     // 4 warps down M
    const int wn = (wid & 1) * 64;      // 2 warps across N
    const uint32_t sbase = smem_u32(smem);

    const __nv_bfloat16* Ahp = Ahi + (size_t)m0 * 512;
    const __nv_bfloat16* Alp = Alo + (size_t)m0 * 512;
    const __nv_bfloat16* Bhp = Bhi + (size_t)n0 * 512;
    const __nv_bfloat16* Blp = Blo + (size_t)n0 * 512;

    float acc[2][8][4];
#pragma unroll
    for (int i = 0; i < 2; i++)
#pragma unroll
        for (int j = 0; j < 8; j++)
#pragma unroll
            for (int l = 0; l < 4; l++) acc[i][j][l] = 0.0f;

#define ISSUE_STAGE(c)                                                        \
    {                                                                         \
        const uint32_t sb0 = sbase + (uint32_t)((c) % NSTAGE) * STAGE_B;      \
        _Pragma("unroll")                                                     \
        for (int s = 0; s < 4; s++) {                                         \
            int idx = tid + s * 256;                                          \
            int row = idx >> 3, uu = idx & 7;                                 \
            uint32_t off = sw_off(row, uu);                                   \
            size_t gof = (size_t)row * 512 + (c) * 64 + uu * 8;               \
            CP16(sb0 + off,              Ahp + gof);                          \
            CP16(sb0 + TILE_B + off,     Alp + gof);                          \
            CP16(sb0 + 2 * TILE_B + off, Bhp + gof);                          \
            CP16(sb0 + 3 * TILE_B + off, Blp + gof);                          \
        }                                                                     \
    }

    ISSUE_STAGE(0); CP_COMMIT();
    ISSUE_STAGE(1); CP_COMMIT();
    ISSUE_STAGE(2); CP_COMMIT();

    for (int c = 0; c < 8; c++) {
        CP_WAIT2();
        __syncthreads();
        const uint32_t sAh = sbase + (uint32_t)(c % NSTAGE) * STAGE_B;
        const uint32_t sAl = sAh + TILE_B;
        const uint32_t sBh = sAh + 2 * TILE_B;
        const uint32_t sBl = sAh + 3 * TILE_B;
#pragma unroll
        for (int k16 = 0; k16 < 4; k16++) {
            const int lrow = lane & 15;
            const int unit = k16 * 2 + (lane >> 4);
            uint32_t ah[2][4], al[2][4], bf[8][2];
#pragma unroll
            for (int mf = 0; mf < 2; mf++) {
                uint32_t off = sw_off(wm + mf * 16 + lrow, unit);
                ldsm4(ah[mf][0], ah[mf][1], ah[mf][2], ah[mf][3], sAh + off);
                ldsm4(al[mf][0], al[mf][1], al[mf][2], al[mf][3], sAl + off);
            }
#pragma unroll
            for (int g = 0; g < 4; g++) {
                uint32_t r0, r1, r2, r3;
                ldsm4(r0, r1, r2, r3, sBh + sw_off(wn + g * 16 + lrow, unit));
                bf[2 * g][0] = r0; bf[2 * g][1] = r2;
                bf[2 * g + 1][0] = r1; bf[2 * g + 1][1] = r3;
            }
#pragma unroll
            for (int mf = 0; mf < 2; mf++)
#pragma unroll
                for (int nf = 0; nf < 8; nf++) {
                    mma16816(acc[mf][nf], ah[mf], bf[nf][0], bf[nf][1]); // ah*bh
                    mma16816(acc[mf][nf], al[mf], bf[nf][0], bf[nf][1]); // al*bh
                }
#pragma unroll
            for (int g = 0; g < 4; g++) {
                uint32_t r0, r1, r2, r3;
                ldsm4(r0, r1, r2, r3, sBl + sw_off(wn + g * 16 + lrow, unit));
                bf[2 * g][0] = r0; bf[2 * g][1] = r2;
                bf[2 * g + 1][0] = r1; bf[2 * g + 1][1] = r3;
            }
#pragma unroll
            for (int mf = 0; mf < 2; mf++)
#pragma unroll
                for (int nf = 0; nf < 8; nf++)
                    mma16816(acc[mf][nf], ah[mf], bf[nf][0], bf[nf][1]); // ah*bl
        }
        __syncthreads();
        if (c + 3 < 8) ISSUE_STAGE(c + 3);
        CP_COMMIT();
    }
#undef ISSUE_STAGE

    // ---------------- epilogue ---------------------------------------------
    const int row0 = m0 + wm + (lane >> 2);
    const int coll = wn + (lane & 3) * 2;
#pragma unroll
    for (int mf = 0; mf < 2; mf++) {
#pragma unroll
        for (int nf = 0; nf < 8; nf++) {
            const int col = n0 + coll + nf * 8;
            const float b0 = bias[col], b1 = bias[col + 1];
            const int rA = row0 + mf * 16;
            const int rB = rA + 8;
            float2 vA = make_float2(acc[mf][nf][0] + b0, acc[mf][nf][1] + b1);
            float2 vB = make_float2(acc[mf][nf][2] + b0, acc[mf][nf][3] + b1);
            if (EPI == 1) {
                vA.x = fmaxf(vA.x, 0.f); vA.y = fmaxf(vA.y, 0.f);
                vB.x = fmaxf(vB.x, 0.f); vB.y = fmaxf(vB.y, 0.f);
                __nv_bfloat162 hA = __floats2bfloat162_rn(vA.x, vA.y);
                __nv_bfloat162 hB = __floats2bfloat162_rn(vB.x, vB.y);
                __nv_bfloat162 lA = __floats2bfloat162_rn(
                    vA.x - __bfloat162float(hA.x), vA.y - __bfloat162float(hA.y));
                __nv_bfloat162 lB = __floats2bfloat162_rn(
                    vB.x - __bfloat162float(hB.x), vB.y - __bfloat162float(hB.y));
                *reinterpret_cast<__nv_bfloat162*>(Chi + (size_t)rA * Ntot + col) = hA;
                *reinterpret_cast<__nv_bfloat162*>(Clo + (size_t)rA * Ntot + col) = lA;
                *reinterpret_cast<__nv_bfloat162*>(Chi + (size_t)rB * Ntot + col) = hB;
                *reinterpret_cast<__nv_bfloat162*>(Clo + (size_t)rB * Ntot + col) = lB;
            } else {
                if (EPI == 2) {
                    const float2 rA2 = *reinterpret_cast<const float2*>(
                        res + (size_t)rA * Ntot + col);
                    const float2 rB2 = *reinterpret_cast<const float2*>(
                        res + (size_t)rB * Ntot + col);
                    vA.x += rA2.x; vA.y += rA2.y;
                    vB.x += rB2.x; vB.y += rB2.y;
                }
                *reinterpret_cast<float2*>(Cf + (size_t)rA * Ntot + col) = vA;
                *reinterpret_cast<float2*>(Cf + (size_t)rB * Ntot + col) = vB;
            }
        }
    }
}

// ===================== LayerNorm -> bf16 hi/lo split =======================
__global__ void ln_split(const float* __restrict__ x,
                         const float* __restrict__ gw,
                         const float* __restrict__ bw,
                         __nv_bfloat16* __restrict__ hi,
                         __nv_bfloat16* __restrict__ lo) {
    int row = blockIdx.x;
    int tid = threadIdx.x;
    const float4* xr = reinterpret_cast<const float4*>(x) + (size_t)row * (HDIM / 4);
    float4 v = xr[tid];
    float s  = v.x + v.y + v.z + v.w;
    float sq = v.x * v.x + v.y * v.y + v.z * v.z + v.w * v.w;
#pragma unroll
    for (int o = 16; o; o >>= 1) {
        s  += __shfl_xor_sync(0xffffffffu, s,  o);
        sq += __shfl_xor_sync(0xffffffffu, sq, o);
    }
    __shared__ float ss[4], sqq[4];
    int w = tid >> 5, l = tid & 31;
    if (l == 0) { ss[w] = s; sqq[w] = sq; }
    __syncthreads();
    s  = ss[0]  + ss[1]  + ss[2]  + ss[3];
    sq = sqq[0] + sqq[1] + sqq[2] + sqq[3];
    float mu  = s * (1.0f / HDIM);
    float var = sq * (1.0f / HDIM) - mu * mu;
    float inv = rsqrtf(var + 1e-5f);
    float4 g4 = reinterpret_cast<const float4*>(gw)[tid];
    float4 b4 = reinterpret_cast<const float4*>(bw)[tid];
    float4 o4;
    o4.x = (v.x - mu) * inv * g4.x + b4.x;
    o4.y = (v.y - mu) * inv * g4.y + b4.y;
    o4.z = (v.z - mu) * inv * g4.z + b4.z;
    o4.w = (v.w - mu) * inv * g4.w + b4.w;
    __nv_bfloat162 h0 = __floats2bfloat162_rn(o4.x, o4.y);
    __nv_bfloat162 h1 = __floats2bfloat162_rn(o4.z, o4.w);
    __nv_bfloat162 l0 = __floats2bfloat162_rn(o4.x - __bfloat162float(h0.x),
                                              o4.y - __bfloat162float(h0.y));
    __nv_bfloat162 l1 = __floats2bfloat162_rn(o4.z - __bfloat162float(h1.x),
                                              o4.w - __bfloat162float(h1.y));
    uint2 hv = make_uint2(*reinterpret_cast<uint32_t*>(&h0),
                          *reinterpret_cast<uint32_t*>(&h1));
    uint2 lv = make_uint2(*reinterpret_cast<uint32_t*>(&l0),
                          *reinterpret_cast<uint32_t*>(&l1));
    reinterpret_cast<uint2*>(hi)[(size_t)row * (HDIM / 4) + tid] = hv;
    reinterpret_cast<uint2*>(lo)[(size_t)row * (HDIM / 4) + tid] = lv;
}

// ====================== weight transpose + split ===========================
__global__ void transpose_split(const float* __restrict__ W,
                                __nv_bfloat16* __restrict__ hi,
                                __nv_bfloat16* __restrict__ lo) {
    __shared__ float tile[32][33];
    int n0 = blockIdx.x * 32, k0 = blockIdx.y * 32;
    tile[threadIdx.y][threadIdx.x] =
        W[(size_t)(k0 + threadIdx.y) * 512 + n0 + threadIdx.x];
    __syncthreads();
    float v = tile[threadIdx.x][threadIdx.y];
    __nv_bfloat16 h = __float2bfloat16(v);
    size_t o = (size_t)(n0 + threadIdx.y) * 512 + k0 + threadIdx.x;
    hi[o] = h;
    lo[o] = __float2bfloat16(v - __bfloat162float(h));
}

__global__ void bias_cat(const float* __restrict__ bz, const float* __restrict__ bh,
                         float* __restrict__ o) {
    int i = threadIdx.x + blockIdx.x * blockDim.x;
    o[i] = (i < 512) ? bz[i] : bh[i - 512];
}

// ============================ gate + scan ==================================
__device__ __forceinline__ void gate_ab(float k, float hp, float& a, float& b) {
    float av = 1.0f / (1.0f + expf(k));     // 1 - sigmoid(k)
    float zv = 1.0f / (1.0f + expf(-k));    // sigmoid(k)
    float gv = (hp >= 0.0f) ? (hp + 0.5f) : 1.0f / (1.0f + expf(-hp));
    a = av; b = zv * gv;
}

__global__ void scan_p1(const float* __restrict__ kh,
                        float* __restrict__ Ac, float* __restrict__ Bc) {
    int h = threadIdx.x, c = blockIdx.x, bb = blockIdx.y;
    size_t base = ((size_t)(bb * TDIM + c * CHUNK)) * 1024 + h;
    float Ap = 1.0f, Bv = 0.0f;
#pragma unroll 4
    for (int t = 0; t < CHUNK; t++) {
        float k  = kh[base + (size_t)t * 1024];
        float hp = kh[base + (size_t)t * 1024 + 512];
        float a, b; gate_ab(k, hp, a, b);
        Bv = fmaf(a, Bv, b);
        Ap *= a;
    }
    int o = (bb * NCH + c) * HDIM + h;
    Ac[o] = Ap; Bc[o] = Bv;
}

__global__ void scan_p2(const float* __restrict__ Ac, const float* __restrict__ Bc,
                        float* __restrict__ Hc) {
    int h = threadIdx.x, bb = blockIdx.x;
    float hcur = 0.5f;              // h_0 = g(0)
    for (int c = 0; c < NCH; c++) {
        int o = (bb * NCH + c) * HDIM + h;
        Hc[o] = hcur;
        hcur = fmaf(Ac[o], hcur, Bc[o]);
    }
}

__global__ void scan_p3(const float* __restrict__ kh, const float* __restrict__ Hc,
                        const float* __restrict__ x, float* __restrict__ x2) {
    int h = threadIdx.x, c = blockIdx.x, bb = blockIdx.y;
    size_t base = ((size_t)(bb * TDIM + c * CHUNK)) * 1024 + h;
    size_t xb   = ((size_t)(bb * TDIM + c * CHUNK)) * 512 + h;
    float hcur = Hc[(bb * NCH + c) * HDIM + h];
#pragma unroll 4
    for (int t = 0; t < CHUNK; t++) {
        float k  = kh[base + (size_t)t * 1024];
        float hp = kh[base + (size_t)t * 1024 + 512];
        float a, b; gate_ab(k, hp, a, b);
        hcur = fmaf(a, hcur, b);
        x2[xb + (size_t)t * 512] = x[xb + (size_t)t * 512] + hcur;
    }
}

// ============================== launch =====================================
extern "C" void kernel_launch(void* const* d_in, const int* in_sizes, int n_in,
                              void* d_out, int out_size) {
    const float* x     = (const float*)d_in[0];
    const float* ln1_g = (const float*)d_in[1];
    const float* ln1_b = (const float*)d_in[2];
    const float* Wz    = (const float*)d_in[3];
    const float* bz    = (const float*)d_in[4];
    const float* Wh    = (const float*)d_in[5];
    const float* bh    = (const float*)d_in[6];
    const float* ln2_g = (const float*)d_in[7];
    const float* ln2_b = (const float*)d_in[8];
    const float* W1    = (const float*)d_in[9];
    const float* b1    = (const float*)d_in[10];
    const float* W2    = (const float*)d_in[11];
    const float* b2    = (const float*)d_in[12];
    float* out = (float*)d_out;

    __nv_bfloat16 *pAhi, *pAlo, *pH1h, *pH1l, *pWzhh, *pWzhl, *pW1h, *pW1l, *pW2h, *pW2l;
    float *pKH, *pX2, *pBzh, *pAc, *pBc, *pHc;
    cudaGetSymbolAddress((void**)&pAhi,  g_Ahi);
    cudaGetSymbolAddress((void**)&pAlo,  g_Alo);
    cudaGetSymbolAddress((void**)&pH1h,  g_H1hi);
    cudaGetSymbolAddress((void**)&pH1l,  g_H1lo);
    cudaGetSymbolAddress((void**)&pWzhh, g_Wzhh);
    cudaGetSymbolAddress((void**)&pWzhl, g_Wzhl);
    cudaGetSymbolAddress((void**)&pW1h,  g_W1h);
    cudaGetSymbolAddress((void**)&pW1l,  g_W1l);
    cudaGetSymbolAddress((void**)&pW2h,  g_W2h);
    cudaGetSymbolAddress((void**)&pW2l,  g_W2l);
    cudaGetSymbolAddress((void**)&pKH,   g_kh);
    cudaGetSymbolAddress((void**)&pX2,   g_x2);
    cudaGetSymbolAddress((void**)&pBzh,  g_bzh);
    cudaGetSymbolAddress((void**)&pAc,   g_Ac);
    cudaGetSymbolAddress((void**)&pBc,   g_Bc);
    cudaGetSymbolAddress((void**)&pHc,   g_Hc);

    cudaFuncSetAttribute(mma_gemm<0>, cudaFuncAttributeMaxDynamicSharedMemorySize, SMEM_TOT);
    cudaFuncSetAttribute(mma_gemm<1>, cudaFuncAttributeMaxDynamicSharedMemorySize, SMEM_TOT);
    cudaFuncSetAttribute(mma_gemm<2>, cudaFuncAttributeMaxDynamicSharedMemorySize, SMEM_TOT);

    dim3 tb(32, 32);
    dim3 tg(16, 16);
    transpose_split<<<tg, tb>>>(Wz, pWzhh, pWzhl);
    transpose_split<<<tg, tb>>>(Wh, pWzhh + 512 * 512, pWzhl + 512 * 512);
    transpose_split<<<tg, tb>>>(W1, pW1h, pW1l);
    transpose_split<<<tg, tb>>>(W2, pW2h, pW2l);
    bias_cat<<<4, 256>>>(bz, bh, pBzh);

    // LN1 -> split
    ln_split<<<MDIM, 128>>>(x, ln1_g, ln1_b, pAhi, pAlo);
    // [k | hpre] = LN1(x) @ [Wz | Wh] + [bz | bh]
    mma_gemm<0><<<dim3(8, MDIM / 128), 256, SMEM_TOT>>>(
        pAhi, pAlo, pWzhh, pWzhl, pBzh, nullptr, pKH, nullptr, nullptr, 1024);
    // chunked linear scan (gates inline)
    scan_p1<<<dim3(NCH, BDIM), HDIM>>>(pKH, pAc, pBc);
    scan_p2<<<BDIM, HDIM>>>(pAc, pBc, pHc);
    scan_p3<<<dim3(NCH, BDIM), HDIM>>>(pKH, pHc, x, pX2);
    // LN2 -> split
    ln_split<<<MDIM, 128>>>(pX2, ln2_g, ln2_b, pAhi, pAlo);
    // h1 = relu(LN2 @ W1 + b1) -> bf16 hi/lo
    mma_gemm<1><<<dim3(4, MDIM / 128), 256, SMEM_TOT>>>(
        pAhi, pAlo, pW1h, pW1l, b1, nullptr, nullptr, pH1h, pH1l, 512);
    // out = x2 + h1 @ W2 + b2
    mma_gemm<2><<<dim3(4, MDIM / 128), 256, SMEM_TOT>>>(
        pH1h, pH1l, pW2h, pW2l, b2, pX2, out, nullptr, nullptr, 512);
}